// round 13
// baseline (speedup 1.0000x reference)
#include <cuda_runtime.h>
#include <math.h>

#define BATCH 32
#define H 512
#define W 512
#define NPIX (H*W)
#define EPSF 1e-4f
#define RSTRIP 16
#define NTHR 128

#define RGB_BLKS 32            // strips per batch = H / RSTRIP = 512/16 = 32
#define DEP_BLKS 16            // depth slices per batch
#define ARRIVALS (RGB_BLKS + DEP_BLKS)

// ---------------- per-block partial outputs (device globals) -------------------
// STATELESS DATA: every partial slot is unconditionally overwritten each
// invocation before it is read. g_cnt is zero at entry and restored to zero
// by the finalizer, so every invocation sees the same initial state.
__device__ int   g_hist_part[BATCH][RGB_BLKS][256];   // per-strip histograms
__device__ float g_lap_part [BATCH][RGB_BLKS][2];     // per-strip (sum, sumsq)
__device__ float g_dep_part [BATCH][DEP_BLKS][3];     // per-slice (n, sum, sumsq)
__device__ unsigned int g_cnt[BATCH];                 // zero-init; self-restoring

__device__ __forceinline__ float warp_sum(float v) {
    #pragma unroll
    for (int o = 16; o > 0; o >>= 1) v += __shfl_down_sync(0xffffffffu, v, o);
    return v;
}

__device__ __forceinline__ float gray_scalar(const float* __restrict__ base,
                                             int gr, int c) {
    float r = __ldg(base + (size_t)gr * W + c);
    float g = __ldg(base + NPIX + (size_t)gr * W + c);
    float b = __ldg(base + 2 * NPIX + (size_t)gr * W + c);
    return 0.299f * r + 0.587f * g + 0.114f * b;
}

// load gray quad for row gr, quad column tid (cols 4*tid..4*tid+3), plus
// boundary scalars for lane 0 (left neighbor) / lane 31 (right neighbor).
// Out-of-image rows -> all zeros (matches zero-padded convolution).
__device__ __forceinline__ void gray_row(const float* __restrict__ base,
                                         int gr, int tid, int lane,
                                         float4& q, float& bl, float& br) {
    bl = 0.0f; br = 0.0f;
    if (gr >= 0 && gr < H) {
        const float4* rp = (const float4*)(base + (size_t)gr * W);
        const float4* gp = (const float4*)(base + NPIX + (size_t)gr * W);
        const float4* bp = (const float4*)(base + 2 * NPIX + (size_t)gr * W);
        float4 r  = __ldg(rp + tid);
        float4 g  = __ldg(gp + tid);
        float4 bq = __ldg(bp + tid);
        q.x = 0.299f * r.x + 0.587f * g.x + 0.114f * bq.x;
        q.y = 0.299f * r.y + 0.587f * g.y + 0.114f * bq.y;
        q.z = 0.299f * r.z + 0.587f * g.z + 0.114f * bq.z;
        q.w = 0.299f * r.w + 0.587f * g.w + 0.114f * bq.w;
        if (lane == 0 && tid > 0)           bl = gray_scalar(base, gr, 4 * tid - 1);
        if (lane == 31 && 4 * tid + 4 < W)  br = gray_scalar(base, gr, 4 * tid + 4);
    } else {
        q.x = q.y = q.z = q.w = 0.0f;
    }
}

// ---------------- single fused kernel ------------------------------------------
// grid: (ARRIVALS, BATCH), block: 128
//   blockIdx.x <  RGB_BLKS : rgb strip (register-sliding laplacian + histogram)
//   blockIdx.x >= RGB_BLKS : depth slice
// Last-arriving block per batch finalizes that batch.
__global__ __launch_bounds__(NTHR) void fused_kernel(
    const float* __restrict__ rgb,
    const float* __restrict__ depth,
    float* __restrict__ out)
{
    __shared__ int   shist[256 * 4];   // [bin][replica], replica = lane & 3
    __shared__ float sred[12];
    __shared__ int   s_last;

    const int b   = blockIdx.y;
    const int bx  = blockIdx.x;
    const int tid = threadIdx.x;       // 0..127 : quad column index (4 cols each)
    const int lane = tid & 31, w = tid >> 5;

    if (bx < RGB_BLKS) {
        // ========== RGB: register-sliding laplacian + interleaved histogram ===
        #pragma unroll
        for (int i = tid; i < 1024; i += NTHR) shist[i] = 0;
        __syncthreads();

        const int rs = bx * RSTRIP;
        const float* base = rgb + (size_t)b * 3 * NPIX;
        const int rep = lane & 3;

        float4 gp, gc, gn;
        float dum0, dum1, blc, brc, bln, brn;
        gray_row(base, rs - 1, tid, lane, gp, dum0, dum1);  // prev (halo)
        gray_row(base, rs,     tid, lane, gc, blc, brc);    // cur

        float s1 = 0.0f, s2 = 0.0f;
        #pragma unroll 2
        for (int r = 0; r < RSTRIP; r++) {
            gray_row(base, rs + r + 1, tid, lane, gn, bln, brn);  // next

            float left  = __shfl_up_sync(0xffffffffu, gc.w, 1);
            if (lane == 0)  left = blc;
            float right = __shfl_down_sync(0xffffffffu, gc.x, 1);
            if (lane == 31) right = brc;

            float lx = gp.x + gn.x + left + gc.y - 4.0f * gc.x;
            float ly = gp.y + gn.y + gc.x + gc.z - 4.0f * gc.y;
            float lz = gp.z + gn.z + gc.y + gc.w - 4.0f * gc.z;
            float lw = gp.w + gn.w + gc.z + right - 4.0f * gc.w;
            s1 += (lx + ly) + (lz + lw);
            s2 += lx * lx + ly * ly + lz * lz + lw * lw;

            int b0 = (int)fminf(fmaxf(gc.x * 255.0f, 0.0f), 255.0f);
            int b1 = (int)fminf(fmaxf(gc.y * 255.0f, 0.0f), 255.0f);
            int b2 = (int)fminf(fmaxf(gc.z * 255.0f, 0.0f), 255.0f);
            int b3 = (int)fminf(fmaxf(gc.w * 255.0f, 0.0f), 255.0f);
            atomicAdd(&shist[b0 * 4 + rep], 1);
            atomicAdd(&shist[b1 * 4 + rep], 1);
            atomicAdd(&shist[b2 * 4 + rep], 1);
            atomicAdd(&shist[b3 * 4 + rep], 1);

            gp = gc; gc = gn; blc = bln; brc = brn;
        }

        s1 = warp_sum(s1);
        s2 = warp_sum(s2);
        if (lane == 0) { sred[w] = s1; sred[4 + w] = s2; }
        __syncthreads();   // also makes shist final for the stores below
        if (tid == 0) {
            g_lap_part[b][bx][0] = sred[0] + sred[1] + sred[2] + sred[3];
            g_lap_part[b][bx][1] = sred[4] + sred[5] + sred[6] + sred[7];
        }
        #pragma unroll
        for (int bin = tid; bin < 256; bin += NTHR) {
            g_hist_part[b][bx][bin] = shist[bin * 4] + shist[bin * 4 + 1]
                                    + shist[bin * 4 + 2] + shist[bin * 4 + 3];
        }
    } else {
        // ================= depth: masked partial sums =========================
        const int part = bx - RGB_BLKS;
        const float4* d4 = (const float4*)(depth + (size_t)b * NPIX);
        const int per = (NPIX / 4) / DEP_BLKS;   // 4096 float4 per slice

        float n = 0.0f, s1 = 0.0f, s2 = 0.0f;
        #pragma unroll 4
        for (int k = 0; k < per / NTHR; k++) {
            float4 v = __ldg(d4 + part * per + k * NTHR + tid);
            if (v.x > 0.0f) { n += 1.0f; s1 += v.x; s2 += v.x * v.x; }
            if (v.y > 0.0f) { n += 1.0f; s1 += v.y; s2 += v.y * v.y; }
            if (v.z > 0.0f) { n += 1.0f; s1 += v.z; s2 += v.z * v.z; }
            if (v.w > 0.0f) { n += 1.0f; s1 += v.w; s2 += v.w * v.w; }
        }
        n  = warp_sum(n);
        s1 = warp_sum(s1);
        s2 = warp_sum(s2);
        if (lane == 0) { sred[w] = n; sred[4 + w] = s1; sred[8 + w] = s2; }
        __syncthreads();
        if (tid == 0) {
            g_dep_part[b][part][0] = sred[0] + sred[1] + sred[2] + sred[3];
            g_dep_part[b][part][1] = sred[4] + sred[5] + sred[6] + sred[7];
            g_dep_part[b][part][2] = sred[8] + sred[9] + sred[10] + sred[11];
        }
    }

    // ================= arrival (release) =====================================
    __syncthreads();          // all partial stores of this block issued
    __threadfence();          // every thread fences its own global stores
    __syncthreads();          // fences complete before the release arrive
    if (tid == 0) {
        unsigned int old = atomicAdd(&g_cnt[b], 1u);
        s_last = (old == ARRIVALS - 1) ? 1 : 0;
    }
    __syncthreads();
    if (!s_last) return;

    // ================= finalize (acquire) — last block for batch b ===========
    __threadfence();

    float e = 0.0f;
    #pragma unroll
    for (int k = 0; k < 2; k++) {
        int bin = tid + k * NTHR;
        int cnt = 0;
        #pragma unroll
        for (int s = 0; s < RGB_BLKS; s++) cnt += __ldcg(&g_hist_part[b][s][bin]);
        float p = (float)cnt * (1.0f / (float)NPIX);
        e += -p * log2f(p + EPSF);
    }
    e = warp_sum(e);
    if (lane == 0) sred[w] = e;
    __syncthreads();
    if (tid == 0) {
        float entropy = sred[0] + sred[1] + sred[2] + sred[3];

        float s1 = 0.0f, s2 = 0.0f, dn = 0.0f, ds1 = 0.0f, ds2 = 0.0f;
        #pragma unroll
        for (int s = 0; s < RGB_BLKS; s++) {
            s1 += __ldcg(&g_lap_part[b][s][0]);
            s2 += __ldcg(&g_lap_part[b][s][1]);
        }
        #pragma unroll
        for (int s = 0; s < DEP_BLKS; s++) {
            dn  += __ldcg(&g_dep_part[b][s][0]);
            ds1 += __ldcg(&g_dep_part[b][s][1]);
            ds2 += __ldcg(&g_dep_part[b][s][2]);
        }

        const float N = (float)NPIX;
        float lvar = (s2 - s1 * s1 / N) / (N - 1.0f);
        float clarity = lvar / (1000.0f + EPSF);
        float uniformity = 1.0f / (entropy + EPSF);
        float rgb_conf = 0.5f * (clarity + uniformity);

        float density = dn / N;
        float mean = ds1 / fmaxf(dn, 1.0f);
        float sq = ds2 - 2.0f * mean * ds1 + mean * mean * dn;
        float dvar = sq / fmaxf(dn - 1.0f, 1.0f);
        float dstd = sqrtf(fmaxf(dvar, 0.0f));
        float noise = (dn > 0.0f) ? dstd : 1.0f;
        float density_score = density / (10000.0f + EPSF);
        float noise_score = 1.0f / (noise + EPSF);
        float depth_conf = 0.5f * (density_score + noise_score);

        float denom = rgb_conf + depth_conf + EPSF;
        out[b]         = rgb_conf / denom;    // w_r
        out[BATCH + b] = depth_conf / denom;  // w_d

        g_cnt[b] = 0u;   // restore invariant: counter is 0 between invocations
    }
}

// ---------------- launch -------------------------------------------------------
extern "C" void kernel_launch(void* const* d_in, const int* in_sizes, int n_in,
                              void* d_out, int out_size) {
    const float* rgb   = (const float*)d_in[0];
    const float* depth = (const float*)d_in[1];
    float* out = (float*)d_out;

    dim3 grid(ARRIVALS, BATCH);
    fused_kernel<<<grid, NTHR>>>(rgb, depth, out);
}